// round 1
// baseline (speedup 1.0000x reference)
#include <cuda_runtime.h>

// SimpleQNN analytic collapse:
//  - state after (RY(x), H, RY(ry), RX(rx)) layers is a product state
//  - CRZ / CZ / RZ are diagonal -> irrelevant to |psi|^2 (rz/crz inputs unused)
//  - CNOT chain is a GF(2) bit permutation: measured Z_w becomes a parity
//    observable over initial wires:  M_0 = {1..15}, M_w = {0..w} (w>=1)
//  - E[parity over M] on a product state = prod_{j in M} z_j
//    with z_j = cos(rx_j) * (a0^2 - a1^2), a = RY(ry_j) H RY(x_bj) |0>
// Then out = q @ W^T + bias.

#define NW 16
#define NOUT 10
#define BATCH 64

__global__ void qnn_analytic_kernel(const float* __restrict__ x,     // [64,16]
                                    const float* __restrict__ ryp,   // [16]
                                    const float* __restrict__ rxp,   // [16]
                                    const float* __restrict__ W,     // [10,16]
                                    const float* __restrict__ bias,  // [10]
                                    float* __restrict__ out)         // [64,10]
{
    const int b = threadIdx.x;
    if (b >= BATCH) return;

    const float inv_sqrt2 = 0.7071067811865475244f;

    float z[NW];
#pragma unroll
    for (int j = 0; j < NW; ++j) {
        // |0> --RY(x)--> (cos(x/2), sin(x/2))
        float u0, u1;
        sincosf(0.5f * x[b * NW + j], &u1, &u0);   // u1 = sin, u0 = cos
        // H
        float h0 = (u0 + u1) * inv_sqrt2;
        float h1 = (u0 - u1) * inv_sqrt2;
        // RY(ry_j): [[C,-S],[S,C]]
        float S, C;
        sincosf(0.5f * ryp[j], &S, &C);
        float a0 = C * h0 - S * h1;
        float a1 = S * h0 + C * h1;
        // RX(rx_j) then Z-expectation: z = cos(rx) * (a0^2 - a1^2)
        z[j] = cosf(rxp[j]) * (a0 * a0 - a1 * a1);
    }

    // q[w] = prod_{0..w} z  (w>=1);  q[0] = prod_{1..15} z  (suffix, no division)
    float q[NW];
    float pref = 1.0f;
#pragma unroll
    for (int w = 0; w < NW; ++w) {
        pref *= z[w];
        q[w] = pref;
    }
    float suf = 1.0f;
#pragma unroll
    for (int j = 1; j < NW; ++j) suf *= z[j];
    q[0] = suf;

    // linear head: out[b,k] = bias[k] + sum_w q[w] * W[k,w]
#pragma unroll
    for (int k = 0; k < NOUT; ++k) {
        float acc = bias[k];
#pragma unroll
        for (int w = 0; w < NW; ++w) acc += q[w] * W[k * NW + w];
        out[b * NOUT + k] = acc;
    }
}

extern "C" void kernel_launch(void* const* d_in, const int* in_sizes, int n_in,
                              void* d_out, int out_size)
{
    // metadata order: x, ry_params, rx_params, rz_params, crz_params, W, b
    const float* x    = (const float*)d_in[0];
    const float* ryp  = (const float*)d_in[1];
    const float* rxp  = (const float*)d_in[2];
    // d_in[3] (rz_params) and d_in[4] (crz_params) are provably unused:
    // diagonal gates do not affect computational-basis probabilities.
    const float* W    = (const float*)d_in[5];
    const float* bias = (const float*)d_in[6];
    float* out = (float*)d_out;

    qnn_analytic_kernel<<<1, BATCH>>>(x, ryp, rxp, W, bias, out);
}

// round 2
// speedup vs baseline: 1.9710x; 1.9710x over previous
#include <cuda_runtime.h>

// SimpleQNN analytic collapse (see R0): product state + diagonal gates dead +
// CNOT chain = parity observables:
//   z_j[b] = cos(rx_j) * (a0^2 - a1^2),  a = RY(ry_j) H RY(x_bj) |0>
//   q[b,w] = prod_{j=0..w} z_j  (w>=1),   q[b,0] = prod_{j=1..15} z_j
//   out = q @ W^T + bias
//
// R1 optimization: parallelize trig over (batch, wire) = 1024 threads,
// fast MUFU trig, warp-shuffle scans per 16-lane group (one batch per
// half-warp). No shared memory, no block barriers.

#define NW 16
#define NOUT 10
#define BATCH 64
#define FULL 0xffffffffu

__global__ void __launch_bounds__(BATCH * NW)
qnn_analytic_kernel(const float* __restrict__ x,     // [64,16]
                    const float* __restrict__ ryp,   // [16]
                    const float* __restrict__ rxp,   // [16]
                    const float* __restrict__ W,     // [10,16]
                    const float* __restrict__ bias,  // [10]
                    float* __restrict__ out)         // [64,10]
{
    const int tid = threadIdx.x;          // 0..1023
    const int b   = tid >> 4;             // batch, one per 16-lane group
    const int j   = tid & 15;             // wire within group

    const float inv_sqrt2 = 0.7071067811865475244f;

    // ---- per-(b,j) single-qubit Z expectation (3 fast trig, fully parallel)
    float u0, u1;
    __sincosf(0.5f * x[b * NW + j], &u1, &u0);   // u1=sin, u0=cos
    float h0 = (u0 + u1) * inv_sqrt2;
    float h1 = (u0 - u1) * inv_sqrt2;
    float S, C;
    __sincosf(0.5f * ryp[j], &S, &C);
    float a0 = C * h0 - S * h1;
    float a1 = S * h0 + C * h1;
    float z  = __cosf(rxp[j]) * (a0 * a0 - a1 * a1);

    // ---- inclusive multiply-scan within the 16-lane group: p = z0*...*zj
    float p = z;
#pragma unroll
    for (int d = 1; d < 16; d <<= 1) {
        float t = __shfl_up_sync(FULL, p, d, 16);
        if (j >= d) p *= t;
    }

    // ---- second scan with z0 masked to 1: lane15 holds prod_{1..15} = q[0]
    float m = (j == 0) ? 1.0f : z;
    float s = m;
#pragma unroll
    for (int d = 1; d < 16; d <<= 1) {
        float t = __shfl_up_sync(FULL, s, d, 16);
        if (j >= d) s *= t;
    }
    float q0 = __shfl_sync(FULL, s, 15, 16);     // broadcast within group

    float q = (j == 0) ? q0 : p;                 // q[b, j]

    // ---- gather full q vector into every lane of the group (16 shfl)
    float qv[NW];
#pragma unroll
    for (int w = 0; w < NW; ++w)
        qv[w] = __shfl_sync(FULL, q, w, 16);

    // ---- linear head: lanes 0..9 each produce one output column
    if (j < NOUT) {
        float acc = bias[j];
#pragma unroll
        for (int w = 0; w < NW; ++w)
            acc = fmaf(qv[w], W[j * NW + w], acc);
        out[b * NOUT + j] = acc;
    }
}

extern "C" void kernel_launch(void* const* d_in, const int* in_sizes, int n_in,
                              void* d_out, int out_size)
{
    // metadata order: x, ry_params, rx_params, rz_params, crz_params, W, b
    const float* x    = (const float*)d_in[0];
    const float* ryp  = (const float*)d_in[1];
    const float* rxp  = (const float*)d_in[2];
    // d_in[3] (rz) / d_in[4] (crz): diagonal gates, provably no effect on probs
    const float* W    = (const float*)d_in[5];
    const float* bias = (const float*)d_in[6];
    float* out = (float*)d_out;

    qnn_analytic_kernel<<<1, BATCH * NW>>>(x, ryp, rxp, W, bias, out);
}